// round 1
// baseline (speedup 1.0000x reference)
#include <cuda_runtime.h>

#define WW 512
#define NB 16
#define NPIX (WW * WW)
#define NITERS 10

// Persistent scratch state (no allocations allowed in kernel_launch).
__device__ float g_tA[NB * NPIX];
__device__ float g_tB[NB * NPIX];
__device__ float g_sed[NB * NPIX];
__device__ float g_wat[NB * NPIX];
__device__ float g_vel[NB * NPIX];

template <bool FIRST, bool LAST>
__global__ void __launch_bounds__(256) erosion_step(
    const float* __restrict__ inp,    // input_terrain (B,1,W,W)
    const float* __restrict__ rain,   // rain plane for this iter (W,W), batch-shared
    const float* __restrict__ p_rr,
    const float* __restrict__ p_ev,
    const float* __restrict__ p_mhd,
    const float* __restrict__ p_heps,
    const float* __restrict__ p_grav,
    const float* __restrict__ p_scc,
    const float* __restrict__ p_diss,
    const float* __restrict__ p_depo,
    float* __restrict__ outp,         // d_out (used only when LAST)
    int pp)                           // ping-pong selector
{
    const float CELL_W = 200.0f / 512.0f;  // 0.390625 exact

    int idx  = blockIdx.x * blockDim.x + threadIdx.x;  // 0..NPIX-1
    int b    = blockIdx.y;
    int base = b * NPIX;
    int c    = idx & (WW - 1);
    int r    = idx >> 9;

    const float* tin  = FIRST ? nullptr : (pp ? g_tB : g_tA);
    float*       tout = LAST  ? nullptr : (pp ? g_tA : g_tB);

    // Terrain read: iteration 0 reads (1 - input)/2 on the fly.
    auto T = [&](int rr, int cc) -> float {
        int j = base + rr * WW + cc;
        if (FIRST) return (1.0f - __ldg(&inp[j])) * 0.5f;
        return __ldg(&tin[j]);
    };

    float t00 = T(r, c);

    // simple_gradient (note: factor = relu(EPS - mag) is always exactly 0,
    // since mag >= sqrt(1e-11) ~ 3.16e-6 > 1e-10, so the noise path is dead).
    float dx, dy;
    if (r == 0)            dx = 0.5f * (t00 * 1.1f - t00);
    else if (r == WW - 1)  dx = 0.5f * (t00 * 0.9f - t00);
    else                   dx = 0.5f * (T(r + 1, c) - T(r - 1, c));
    if (c == 0)            dy = 0.5f * (t00 * 1.1f - t00);
    else if (c == WW - 1)  dy = 0.5f * (t00 * 0.9f - t00);
    else                   dy = 0.5f * (T(r, c + 1) - T(r, c - 1));

    float mag = __fsqrt_rn(dx * dx + dy * dy + 1e-11f);
    float fdx = __fdiv_rn(dx, mag);
    float fdy = __fdiv_rn(dy, mag);

    // bilinear_sample(terrain, -gradient)
    float fx  = (float)c - fdx;
    float fy  = (float)r - fdy;
    float x0f = floorf(fx), y0f = floorf(fy);
    int   x0  = (int)x0f,  y0  = (int)y0f;
    float wx1 = fx - x0f,  wy1 = fy - y0f;

    auto G = [&](int ix, int iy) -> float {
        bool valid = (ix >= 0) & (ix < WW) & (iy >= 0) & (iy < WW);
        int ixc = min(max(ix, 0), WW - 1);
        int iyc = min(max(iy, 0), WW - 1);
        float v = T(iyc, ixc) - 1.0f;
        return valid ? v : 0.0f;
    };
    float v00 = G(x0,     y0);
    float v10 = G(x0 + 1, y0);
    float v01 = G(x0,     y0 + 1);
    float v11 = G(x0 + 1, y0 + 1);
    float nbv = (1.0f - wy1) * ((1.0f - wx1) * v00 + wx1 * v10)
              + wy1 * ((1.0f - wx1) * v01 + wx1 * v11) + 1.0f;

    float hd = t00 - nbv;

    float sed = FIRST ? 0.0f : g_sed[base + idx];
    float wat = FIRST ? 0.0f : g_wat[base + idx];
    float vel = FIRST ? 0.0f : g_vel[base + idx];

    // water += relu(rain_rate) * rain
    wat += fmaxf(__ldg(p_rr), 0.0f) * __ldg(&rain[idx]);

    float heps = __ldg(p_heps);
    float mhd  = __ldg(p_mhd);
    float scc  = fmaxf(__ldg(p_scc), 0.0f);

    float hds     = (hd - heps > 0.0f) ? 1.0f : 0.0f;      // sign(relu(hd - heps))
    float nhd     = hds * fmaxf(hd, mhd);
    float sed_cap = __fdiv_rn(nhd, CELL_W) * vel * wat * scc;
    float ftb     = (hd < 0.0f) ? 1.0f : 0.0f;             // relu(sign(-hd))
    float first   = fminf(fmaxf(-hd, 0.0f), sed);
    float sdiff   = sed - sed_cap;
    float depo    = __ldg(p_depo);
    float diss    = __ldg(p_diss);
    float third   = (1.0f - ftb) *
                    (fmaxf(sdiff * depo, 0.0f) - fmaxf(-sdiff * diss, 0.0f));
    float dep     = fmaxf(-fmaxf(hd, 0.0f), first + third);

    sed        = sed - dep;
    float tnew = t00 + dep;

    // displace (pointwise; edge-column masks)
    float m1 = fmaxf(-fdy, 0.0f); if (c == WW - 1) m1 = 0.0f;
    float m2 = fmaxf(1.0f - fabsf(fdy), 0.0f);
    float m3 = fmaxf(fdy, 0.0f);  if (c == 0)      m3 = 0.0f;

    float s1 = m1 * sed, s2 = m2 * sed, s3 = m3 * sed;
    sed = (s1 + s2) + s3;
    float w1 = m1 * wat, w2 = m2 * wat, w3 = m3 * wat;
    wat = (w1 + w2) + w3;

    // velocity = relu(gravity) * hd / CELL_W
    float grav = fmaxf(__ldg(p_grav), 0.0f);
    vel = __fdiv_rn(grav * hd, CELL_W);

    // water *= (1 - relu(evaporation))
    float ev = fmaxf(__ldg(p_ev), 0.0f);
    wat = wat * (1.0f - ev);

    if (LAST) {
        // relu(1 + (1 - 2*t)) - 1, straight to d_out
        outp[base + idx] = fmaxf(1.0f + (1.0f - tnew * 2.0f), 0.0f) - 1.0f;
    } else {
        tout[base + idx]  = tnew;
        g_sed[base + idx] = sed;
        g_wat[base + idx] = wat;
        g_vel[base + idx] = vel;
    }
}

extern "C" void kernel_launch(void* const* d_in, const int* in_sizes, int n_in,
                              void* d_out, int out_size) {
    const float* inp      = (const float*)d_in[0];
    const float* rainfall = (const float*)d_in[1];  // (1, ITERS, W, W)
    // d_in[2] = random_gradient: mathematically dead (factor == 0 always)
    const float* p_rr   = (const float*)d_in[3];
    const float* p_ev   = (const float*)d_in[4];
    const float* p_mhd  = (const float*)d_in[5];
    const float* p_heps = (const float*)d_in[6];
    const float* p_grav = (const float*)d_in[7];
    const float* p_scc  = (const float*)d_in[8];
    const float* p_diss = (const float*)d_in[9];
    const float* p_depo = (const float*)d_in[10];
    float* outp = (float*)d_out;

    dim3 grid(NPIX / 256, NB);
    dim3 block(256);

    for (int it = 0; it < NITERS; ++it) {
        const float* rain = rainfall + it * NPIX;
        int pp = it & 1;
        if (it == 0) {
            erosion_step<true, false><<<grid, block>>>(
                inp, rain, p_rr, p_ev, p_mhd, p_heps, p_grav, p_scc, p_diss,
                p_depo, outp, pp);
        } else if (it == NITERS - 1) {
            erosion_step<false, true><<<grid, block>>>(
                inp, rain, p_rr, p_ev, p_mhd, p_heps, p_grav, p_scc, p_diss,
                p_depo, outp, pp);
        } else {
            erosion_step<false, false><<<grid, block>>>(
                inp, rain, p_rr, p_ev, p_mhd, p_heps, p_grav, p_scc, p_diss,
                p_depo, outp, pp);
        }
    }
}

// round 3
// speedup vs baseline: 2.6916x; 2.6916x over previous
#include <cuda_runtime.h>

#define WW 512
#define NB 16
#define NPIX (WW * WW)
#define NITERS 10
#define INV_CELL 2.56f        // 1 / (200/512)
#define CELLW    0.390625f

// Persistent scratch state (no allocations allowed in kernel_launch).
__device__ float g_tA[NB * NPIX];
__device__ float g_tB[NB * NPIX];
__device__ float g_sed[NB * NPIX];
__device__ float g_wat[NB * NPIX];
__device__ float g_vel[NB * NPIX];

template <bool FIRST>
__device__ __forceinline__ float tval(float v) {
    return FIRST ? (1.0f - v) * 0.5f : v;
}

template <bool FIRST, bool LAST>
__global__ void __launch_bounds__(256) erosion_step(
    const float* __restrict__ inp,
    const float* __restrict__ rain,   // rain plane for this iter (W,W)
    const float* __restrict__ p_rr,
    const float* __restrict__ p_ev,
    const float* __restrict__ p_mhd,
    const float* __restrict__ p_heps,
    const float* __restrict__ p_grav,
    const float* __restrict__ p_scc,
    const float* __restrict__ p_diss,
    const float* __restrict__ p_depo,
    float* __restrict__ outp,
    int pp)
{
    int tid  = blockIdx.x * blockDim.x + threadIdx.x;   // 0 .. NPIX/4-1
    int b    = blockIdx.y;
    int base = b * NPIX;
    int c4   = (tid & 127) << 2;
    int r    = tid >> 7;
    int rowo = r * WW + c4;

    const float* tin = FIRST ? (inp + base) : ((pp ? g_tB : g_tA) + base);

    // ---- center row (float4) ----
    float4 tcv = __ldg((const float4*)(tin + rowo));
    float ta[4] = { tval<FIRST>(tcv.x), tval<FIRST>(tcv.y),
                    tval<FIRST>(tcv.z), tval<FIRST>(tcv.w) };

    // ---- dx (row stencil) ----
    float dxa[4];
    if (r == 0) {
        #pragma unroll
        for (int i = 0; i < 4; i++) dxa[i] = 0.5f * (ta[i] * 1.1f - ta[i]);
    } else if (r == WW - 1) {
        #pragma unroll
        for (int i = 0; i < 4; i++) dxa[i] = 0.5f * (ta[i] * 0.9f - ta[i]);
    } else {
        float4 tu = __ldg((const float4*)(tin + rowo - WW));
        float4 td = __ldg((const float4*)(tin + rowo + WW));
        dxa[0] = 0.5f * (tval<FIRST>(td.x) - tval<FIRST>(tu.x));
        dxa[1] = 0.5f * (tval<FIRST>(td.y) - tval<FIRST>(tu.y));
        dxa[2] = 0.5f * (tval<FIRST>(td.z) - tval<FIRST>(tu.z));
        dxa[3] = 0.5f * (tval<FIRST>(td.w) - tval<FIRST>(tu.w));
    }

    // ---- dy (column stencil within float4 + 2 halo scalars) ----
    float tl = (c4 > 0)   ? tval<FIRST>(__ldg(tin + rowo - 1)) : 0.0f;
    float tr = (c4 < 508) ? tval<FIRST>(__ldg(tin + rowo + 4)) : 0.0f;
    float dya[4];
    dya[0] = (c4 == 0)   ? 0.5f * (ta[0] * 1.1f - ta[0]) : 0.5f * (ta[1] - tl);
    dya[1] = 0.5f * (ta[2] - ta[0]);
    dya[2] = 0.5f * (ta[3] - ta[1]);
    dya[3] = (c4 == 508) ? 0.5f * (ta[3] * 0.9f - ta[3]) : 0.5f * (tr - ta[2]);

    bool interior = (r >= 1) && (r <= 509) && (c4 >= 4) && (c4 <= 504);

    // ---- scalar params (hoisted, amortized over 4 cells) ----
    float rr   = fmaxf(__ldg(p_rr), 0.0f);
    float ev   = fmaxf(__ldg(p_ev), 0.0f);
    float grav = fmaxf(__ldg(p_grav), 0.0f);
    float heps = 0.0f, mhd = 0.0f, scc = 0.0f, diss = 0.0f, depo = 0.0f;
    if (!FIRST) {
        heps = __ldg(p_heps);
        mhd  = __ldg(p_mhd);
        scc  = fmaxf(__ldg(p_scc), 0.0f);
        diss = __ldg(p_diss);
        depo = __ldg(p_depo);
    }

    float4 rn4 = __ldg((const float4*)(rain + rowo));
    float rna[4] = { rn4.x, rn4.y, rn4.z, rn4.w };

    float seda[4] = {0, 0, 0, 0}, wata[4] = {0, 0, 0, 0}, vela[4] = {0, 0, 0, 0};
    if (!FIRST) {
        float4 s4 = __ldg((const float4*)(g_sed + base + rowo));
        float4 w4 = __ldg((const float4*)(g_wat + base + rowo));
        float4 v4 = __ldg((const float4*)(g_vel + base + rowo));
        seda[0] = s4.x; seda[1] = s4.y; seda[2] = s4.z; seda[3] = s4.w;
        wata[0] = w4.x; wata[1] = w4.y; wata[2] = w4.z; wata[3] = w4.w;
        vela[0] = v4.x; vela[1] = v4.y; vela[2] = v4.z; vela[3] = v4.w;
    }

    float oT[4], oS[4], oW[4], oV[4];

    #pragma unroll
    for (int i = 0; i < 4; i++) {
        int   c   = c4 + i;
        float t00 = ta[i];
        float dx  = dxa[i], dy = dya[i];

        // normalized gradient (factor == 0 always; noise path dead)
        float inv = rsqrtf(dx * dx + dy * dy + 1e-11f);
        float fdx = dx * inv;
        float fdy = dy * inv;

        // bilinear_sample(terrain, -gradient)
        float fx  = (float)c - fdx;
        float fy  = (float)r - fdy;
        float x0f = floorf(fx), y0f = floorf(fy);
        int   x0  = (int)x0f,  y0  = (int)y0f;
        float wx1 = fx - x0f,  wy1 = fy - y0f;

        float v00, v10, v01, v11;
        if (interior) {
            const float* p = tin + y0 * WW + x0;
            v00 = tval<FIRST>(__ldg(p))          - 1.0f;
            v10 = tval<FIRST>(__ldg(p + 1))      - 1.0f;
            v01 = tval<FIRST>(__ldg(p + WW))     - 1.0f;
            v11 = tval<FIRST>(__ldg(p + WW + 1)) - 1.0f;
        } else {
            int x1 = x0 + 1, y1 = y0 + 1;
            bool vx0 = (unsigned)x0 < (unsigned)WW;
            bool vx1 = (unsigned)x1 < (unsigned)WW;
            bool vy0 = (unsigned)y0 < (unsigned)WW;
            bool vy1 = (unsigned)y1 < (unsigned)WW;
            int x0c = min(max(x0, 0), WW - 1), x1c = min(max(x1, 0), WW - 1);
            int y0c = min(max(y0, 0), WW - 1), y1c = min(max(y1, 0), WW - 1);
            const float* p0 = tin + y0c * WW;
            const float* p1 = tin + y1c * WW;
            v00 = (vx0 & vy0) ? (tval<FIRST>(__ldg(p0 + x0c)) - 1.0f) : 0.0f;
            v10 = (vx1 & vy0) ? (tval<FIRST>(__ldg(p0 + x1c)) - 1.0f) : 0.0f;
            v01 = (vx0 & vy1) ? (tval<FIRST>(__ldg(p1 + x0c)) - 1.0f) : 0.0f;
            v11 = (vx1 & vy1) ? (tval<FIRST>(__ldg(p1 + x1c)) - 1.0f) : 0.0f;
        }
        float nbv = (1.0f - wy1) * ((1.0f - wx1) * v00 + wx1 * v10)
                  + wy1 * ((1.0f - wx1) * v01 + wx1 * v11) + 1.0f;
        float hd = t00 - nbv;

        if (FIRST) {
            // iter 0: sed == vel == 0 => sed_cap == 0, first == 0, third == 0,
            // dep = max(-relu(hd), 0) = 0.  Terrain unchanged, sediment stays 0.
            float wat = rr * rna[i];
            float m1 = fmaxf(-fdy, 0.0f); if (c == WW - 1) m1 = 0.0f;
            float m2 = fmaxf(1.0f - fabsf(fdy), 0.0f);
            float m3 = fmaxf(fdy, 0.0f);  if (c == 0)      m3 = 0.0f;
            wat = (m1 * wat + m2 * wat) + m3 * wat;
            wat = wat * (1.0f - ev);
            oT[i] = t00;
            oS[i] = 0.0f;
            oW[i] = wat;
            oV[i] = grav * hd * INV_CELL;
        } else {
            float sed = seda[i];
            float wat = wata[i] + rr * rna[i];
            float vel = vela[i];

            float hds     = (hd - heps > 0.0f) ? 1.0f : 0.0f;
            float nhd     = hds * fmaxf(hd, mhd);
            float sed_cap = (nhd * INV_CELL) * vel * wat * scc;
            float ftb     = (hd < 0.0f) ? 1.0f : 0.0f;
            float first   = fminf(fmaxf(-hd, 0.0f), sed);
            float sdiff   = sed - sed_cap;
            float third   = (1.0f - ftb) *
                            (fmaxf(sdiff * depo, 0.0f) - fmaxf(-sdiff * diss, 0.0f));
            float dep     = fmaxf(-fmaxf(hd, 0.0f), first + third);

            float tnew = t00 + dep;
            if (LAST) {
                oT[i] = fmaxf(1.0f + (1.0f - tnew * 2.0f), 0.0f) - 1.0f;
            } else {
                sed = sed - dep;
                float m1 = fmaxf(-fdy, 0.0f); if (c == WW - 1) m1 = 0.0f;
                float m2 = fmaxf(1.0f - fabsf(fdy), 0.0f);
                float m3 = fmaxf(fdy, 0.0f);  if (c == 0)      m3 = 0.0f;
                sed = (m1 * sed + m2 * sed) + m3 * sed;
                wat = (m1 * wat + m2 * wat) + m3 * wat;
                wat = wat * (1.0f - ev);
                oT[i] = tnew;
                oS[i] = sed;
                oW[i] = wat;
                oV[i] = grav * hd * INV_CELL;
            }
        }
    }

    if (LAST) {
        *(float4*)(outp + base + rowo) = make_float4(oT[0], oT[1], oT[2], oT[3]);
    } else {
        float* tout = (pp ? g_tA : g_tB) + base;
        *(float4*)(tout + rowo)          = make_float4(oT[0], oT[1], oT[2], oT[3]);
        *(float4*)(g_sed + base + rowo)  = make_float4(oS[0], oS[1], oS[2], oS[3]);
        *(float4*)(g_wat + base + rowo)  = make_float4(oW[0], oW[1], oW[2], oW[3]);
        *(float4*)(g_vel + base + rowo)  = make_float4(oV[0], oV[1], oV[2], oV[3]);
    }
}

extern "C" void kernel_launch(void* const* d_in, const int* in_sizes, int n_in,
                              void* d_out, int out_size) {
    const float* inp      = (const float*)d_in[0];
    const float* rainfall = (const float*)d_in[1];
    // d_in[2] = random_gradient: mathematically dead (factor == 0 always)
    const float* p_rr   = (const float*)d_in[3];
    const float* p_ev   = (const float*)d_in[4];
    const float* p_mhd  = (const float*)d_in[5];
    const float* p_heps = (const float*)d_in[6];
    const float* p_grav = (const float*)d_in[7];
    const float* p_scc  = (const float*)d_in[8];
    const float* p_diss = (const float*)d_in[9];
    const float* p_depo = (const float*)d_in[10];
    float* outp = (float*)d_out;

    dim3 grid(NPIX / 4 / 256, NB);
    dim3 block(256);

    for (int it = 0; it < NITERS; ++it) {
        const float* rain = rainfall + it * NPIX;
        int pp = it & 1;
        if (it == 0) {
            erosion_step<true, false><<<grid, block>>>(
                inp, rain, p_rr, p_ev, p_mhd, p_heps, p_grav, p_scc, p_diss,
                p_depo, outp, pp);
        } else if (it == NITERS - 1) {
            erosion_step<false, true><<<grid, block>>>(
                inp, rain, p_rr, p_ev, p_mhd, p_heps, p_grav, p_scc, p_diss,
                p_depo, outp, pp);
        } else {
            erosion_step<false, false><<<grid, block>>>(
                inp, rain, p_rr, p_ev, p_mhd, p_heps, p_grav, p_scc, p_diss,
                p_depo, outp, pp);
        }
    }
}